// round 12
// baseline (speedup 1.0000x reference)
#include <cuda_runtime.h>

#define NQ      10
#define DIM     1024
#define TSTEPS  10
#define NDATA   1024
#define NTHREADS 64                // 2 warps = 1 sample, 16 amps/thread
#define AMPS    16

typedef unsigned long long u64;

__device__ __forceinline__ u64 pk(float x, float y) {
    u64 u; asm("mov.b64 %0, {%1,%2};" : "=l"(u) : "f"(x), "f"(y)); return u;
}
__device__ __forceinline__ void upk(u64 u, float &x, float &y) {
    asm("mov.b64 {%0,%1}, %2;" : "=f"(x), "=f"(y) : "l"(u));
}
__device__ __forceinline__ u64 swp(u64 u) { float x, y; upk(u, x, y); return pk(y, x); }
__device__ __forceinline__ u64 ffma2(u64 a, u64 b, u64 c) {
    u64 d; asm("fma.rn.f32x2 %0, %1, %2, %3;" : "=l"(d) : "l"(a), "l"(b), "l"(c)); return d;
}
__device__ __forceinline__ u64 fmul2(u64 a, u64 b) {
    u64 d; asm("mul.rn.f32x2 %0, %1, %2;" : "=l"(d) : "l"(a), "l"(b)); return d;
}

// amp j (10b) = (w<<9)|(lt<<8)|(hi<<4)|(lo) ; qubit i <-> j bit (9-i)
//   w  (1b) = qubit 0 (cross-warp), lt (1b) = qubit 1 (shuffle mask 16)
// Layout A: thread(w,lt,ll) reg r holds j = W|(r<<4)|ll  -> r-field = qubits 2,3,4,5
// Layout B: thread(w,lt,ll) reg r holds j = W|(ll<<4)|r  -> r-field = qubits 6,7,8,9
// smem slot(j) = j with low nibble replaced by (j[3:0] ^ j[7:4])  (conflict-free
// for both layouts' write AND read patterns; verified per 16-lane phase)

struct Ctx {
    u64*    s_x0;
    u64*    s_x1;
    float2* s_rot;
    float*  s_lane;
    float*  s_rphi;
    float*  s_w;
};

// One time step, parity PAR (0: enters layout A; flips to B mid-step)
template<int PAR>
__device__ __forceinline__ void do_step(int tt, u64 (&psi)[AMPS], const Ctx& C,
                                        int w, int lane, int lt, int ll, int k0)
{
    // ---- diagonal E_tt (entry layout; tables layout-aware) ----
    {
        float base = C.s_lane[tt * 32 + lane] + C.s_w[tt * 2 + w];
        const float* rp = C.s_rphi + tt * 176 + k0;
        #pragma unroll
        for (int r = 0; r < AMPS; r++) {
            float ph = base + rp[r * 11 + __popc(r)];
            float sn, cn; __sincosf(ph, &sn, &cn);
            psi[r] = ffma2(pk(-sn, sn), swp(psi[r]), fmul2(pk(cn, cn), psi[r]));
        }
    }
    // ---- reg quad 1 (entry layout): qubits qb1..qb1+3, masks 8,4,2,1 ----
    {
        const int qb1 = PAR ? 6 : 2;
        #pragma unroll
        for (int qq = 0; qq < 4; qq++) {
            const int m = 8 >> qq;
            float2 cs = C.s_rot[tt * NQ + qb1 + qq];
            u64 C2 = pk(cs.x, cs.x), S2 = pk(cs.y, cs.y), Sn = pk(-cs.y, -cs.y);
            #pragma unroll
            for (int rr = 0; rr < AMPS / 2; rr++) {
                int r0 = ((rr & ~(m - 1)) << 1) | (rr & (m - 1));
                int r1 = r0 | m;
                u64 p0 = psi[r0], p1 = psi[r1];
                psi[r0] = ffma2(Sn, p1, fmul2(C2, p0));
                psi[r1] = ffma2(S2, p0, fmul2(C2, p1));
            }
        }
    }
    // ---- shuffle gate: qubit 1 (lane mask 16) ----
    {
        float2 cs = C.s_rot[tt * NQ + 1];
        float so = (lane & 16) ? cs.y : -cs.y;
        u64 C2 = pk(cs.x, cs.x), S2 = pk(so, so);
        #pragma unroll
        for (int r = 0; r < AMPS; r++) {
            float x, y; upk(psi[r], x, y);
            float ox = __shfl_xor_sync(0xFFFFFFFFu, x, 16);
            float oy = __shfl_xor_sync(0xFFFFFFFFu, y, 16);
            psi[r] = ffma2(S2, pk(ox, oy), fmul2(C2, psi[r]));
        }
    }
    // ---- exchange qubit 0 (w bit) WITH layout flip; 1 barrier ----
    {
        u64* buf = PAR ? C.s_x1 : C.s_x0;
        const int wbase = (w << 9) | (lt << 8);
        // write under entry layout
        #pragma unroll
        for (int r = 0; r < AMPS; r++) {
            const int lo = PAR ? ((ll << 4) | (r ^ ll))     // B: j = W|(ll<<4)|r
                              : ((r << 4) | (ll ^ r));      // A: j = W|(r<<4)|ll
            buf[wbase | lo] = psi[r];
        }
        __syncthreads();
        // read own + partner under flipped layout, apply q0 rotation
        float2 cs = C.s_rot[tt * NQ + 0];
        float so = w ? cs.y : -cs.y;
        u64 C2 = pk(cs.x, cs.x), S2 = pk(so, so);
        const int obase = (lt << 8);
        #pragma unroll
        for (int r = 0; r < AMPS; r++) {
            const int lo = PAR ? ((r << 4) | (ll ^ r))      // now A
                              : ((ll << 4) | (r ^ ll));     // now B
            u64 own = buf[(w << 9) | obase | lo];
            u64 par = buf[((w ^ 1) << 9) | obase | lo];
            psi[r] = ffma2(S2, par, fmul2(C2, own));
        }
    }
    // ---- reg quad 2 (flipped layout): the other qubit quad ----
    {
        const int qb2 = PAR ? 2 : 6;
        #pragma unroll
        for (int qq = 0; qq < 4; qq++) {
            const int m = 8 >> qq;
            float2 cs = C.s_rot[tt * NQ + qb2 + qq];
            u64 C2 = pk(cs.x, cs.x), S2 = pk(cs.y, cs.y), Sn = pk(-cs.y, -cs.y);
            #pragma unroll
            for (int rr = 0; rr < AMPS / 2; rr++) {
                int r0 = ((rr & ~(m - 1)) << 1) | (rr & (m - 1));
                int r1 = r0 | m;
                u64 p0 = psi[r0], p1 = psi[r1];
                psi[r0] = ffma2(Sn, p1, fmul2(C2, p0));
                psi[r1] = ffma2(S2, p0, fmul2(C2, p1));
            }
        }
    }
}

__global__ __launch_bounds__(NTHREADS)
void scramble_kernel(const float* __restrict__ in_re,
                     const float* __restrict__ in_im,
                     const float* __restrict__ phis,
                     const float* __restrict__ gs,
                     float* __restrict__ out)
{
    __shared__ u64    s_x[2][DIM];            // double-buffered exchange (by step parity)
    __shared__ float2 s_rot[TSTEPS * NQ];     // (cos(th/2), sin(th/2))
    __shared__ float  s_wgt[11][NQ];          // merged diag weights w_i(t)=a_i(t)+b_i(t-1)
    __shared__ float  s_lane[11 * 32];        // layout-aware lane sums (lt + ll-field)
    __shared__ float  s_rphi[11 * 16 * 11];   // layout-aware r-field sums + popcount phase
    __shared__ float  s_w[11 * 2];            // w sums + (-0.5*total)
    __shared__ float  s_nrm[2];

    const int tid  = threadIdx.x;
    const int w    = tid >> 5;
    const int lane = tid & 31;
    const int lt   = lane >> 4;               // j bit 8 (qubit 1)
    const int ll   = lane & 15;               // 4-bit field
    const int b    = blockIdx.x;
    const float* P = phis + b * 300;

    // ---- rotation coefficients ----
    for (int g = tid; g < 100; g += NTHREADS) {
        int tt = g / NQ, i = g - tt * NQ;
        float th = P[30 * tt + NQ + i];
        float s, c; __sincosf(0.5f * th, &s, &c);
        s_rot[g] = make_float2(c, s);
    }
    // ---- merged diag weights ----
    for (int u = tid; u < 110; u += NTHREADS) {
        int tt = u / NQ, i = u - tt * NQ;
        float v = 0.f;
        if (tt < 10) v += P[30 * tt + i];
        if (tt > 0)  v += P[30 * (tt - 1) + 2 * NQ + i];
        s_wgt[tt][i] = v;
    }
    __syncthreads();
    // ---- lane-sum tables (entry layout of step tt: A if tt even) ----
    for (int idx = tid; idx < 11 * 32; idx += NTHREADS) {
        int tt = idx >> 5, l = idx & 31, la = tt & 1;
        float s = 0.f;
        if (l & 16) s += s_wgt[tt][1];        // lt bit = qubit 1
        if (la == 0) {   // A: ll-field = qubits 6,7,8,9
            if (l & 8) s += s_wgt[tt][6];
            if (l & 4) s += s_wgt[tt][7];
            if (l & 2) s += s_wgt[tt][8];
            if (l & 1) s += s_wgt[tt][9];
        } else {         // B: ll-field = qubits 2,3,4,5
            if (l & 8) s += s_wgt[tt][2];
            if (l & 4) s += s_wgt[tt][3];
            if (l & 2) s += s_wgt[tt][4];
            if (l & 1) s += s_wgt[tt][5];
        }
        s_lane[idx] = s;
    }
    // ---- w-sum tables ----
    for (int idx = tid; idx < 11 * 2; idx += NTHREADS) {
        int tt = idx >> 1, ww = idx & 1;
        float tot = 0.f;
        #pragma unroll
        for (int i = 0; i < NQ; i++) tot += s_wgt[tt][i];
        float s = -0.5f * tot;
        if (ww) s += s_wgt[tt][0];            // w bit = qubit 0
        s_w[idx] = s;
    }
    // ---- r-field-sum + popcount-phase tables ----
    for (int idx = tid; idx < 11 * 16 * 11; idx += NTHREADS) {
        int tt = idx / 176, rem = idx - tt * 176;
        int r = rem / 11, k = rem - r * 11, la = tt & 1;
        float v = 0.f;
        if (la == 0) {   // A: r-field = qubits 2,3,4,5
            if (r & 8) v += s_wgt[tt][2];
            if (r & 4) v += s_wgt[tt][3];
            if (r & 2) v += s_wgt[tt][4];
            if (r & 1) v += s_wgt[tt][5];
        } else {         // B: r-field = qubits 6,7,8,9
            if (r & 8) v += s_wgt[tt][6];
            if (r & 4) v += s_wgt[tt][7];
            if (r & 2) v += s_wgt[tt][8];
            if (r & 1) v += s_wgt[tt][9];
        }
        if (tt > 0) {
            const float inv = 0.15811388300841897f;  // 1/(2*sqrt(10))
            float theta = gs[b * TSTEPS + tt - 1] * inv;
            float zs = 10.f - 2.f * (float)k;
            v += -0.5f * theta * (0.5f * (zs * zs - 10.f));
        }
        s_rphi[idx] = v;
    }

    // ---- load amplitudes (layout A: j = (w<<9)|(lt<<8)|(r<<4)|ll, coalesced) ----
    u64 psi[AMPS];
    float nrm = 0.f;
    #pragma unroll
    for (int r = 0; r < AMPS; r++) {
        int j = (w << 9) | (lt << 8) | (r << 4) | ll;
        float re = in_re[b * DIM + j];
        float im = in_im[b * DIM + j];
        psi[r] = pk(re, im);
        nrm += re * re + im * im;
    }
    #pragma unroll
    for (int off = 16; off; off >>= 1)
        nrm += __shfl_xor_sync(0xFFFFFFFFu, nrm, off);
    if (lane == 0) s_nrm[w] = nrm;
    __syncthreads();                           // also fences table builds
    const float invn = rsqrtf(s_nrm[0] + s_nrm[1]);
    const int k0 = w + __popc(lane);

    Ctx C{ s_x[0], s_x[1], s_rot, s_lane, s_rphi, s_w };

    // ---- 10 steps, parity specialized; one barrier per step ----
    #pragma unroll 1
    for (int th = 0; th < TSTEPS / 2; th++) {
        do_step<0>(2 * th,     psi, C, w, lane, lt, ll, k0);
        do_step<1>(2 * th + 1, psi, C, w, lane, lt, ll, k0);
    }

    // ---- final diagonal E_10 (layout A, la=0) ----
    {
        float base = s_lane[10 * 32 + lane] + s_w[10 * 2 + w];
        const float* rp = s_rphi + 10 * 176 + k0;
        #pragma unroll
        for (int r = 0; r < AMPS; r++) {
            float ph = base + rp[r * 11 + __popc(r)];
            float sn, cn; __sincosf(ph, &sn, &cn);
            psi[r] = ffma2(pk(-sn, sn), swp(psi[r]), fmul2(pk(cn, cn), psi[r]));
        }
    }
    // ---- store (layout A) with deferred normalization ----
    #pragma unroll
    for (int r = 0; r < AMPS; r++) {
        int j = (w << 9) | (lt << 8) | (r << 4) | ll;
        float x, y; upk(psi[r], x, y);
        out[b * DIM + j]               = x * invn;
        out[NDATA * DIM + b * DIM + j] = y * invn;
    }
}

extern "C" void kernel_launch(void* const* d_in, const int* in_sizes, int n_in,
                              void* d_out, int out_size)
{
    const float* in_re = (const float*)d_in[0];
    const float* in_im = (const float*)d_in[1];
    const float* phis  = (const float*)d_in[2];
    const float* gs    = (const float*)d_in[3];
    float* out = (float*)d_out;
    scramble_kernel<<<NDATA, NTHREADS>>>(in_re, in_im, phis, gs, out);
}

// round 16
// speedup vs baseline: 1.6457x; 1.6457x over previous
#include <cuda_runtime.h>

#define NQ      10
#define DIM     1024
#define TSTEPS  10
#define NDATA   1024
#define NTHREADS 128               // 4 warps = 1 sample
#define AMPS    8

typedef unsigned long long u64;

__device__ __forceinline__ u64 pk(float x, float y) {
    u64 u; asm("mov.b64 %0, {%1,%2};" : "=l"(u) : "f"(x), "f"(y)); return u;
}
__device__ __forceinline__ void upk(u64 u, float &x, float &y) {
    asm("mov.b64 {%0,%1}, %2;" : "=f"(x), "=f"(y) : "l"(u));
}
__device__ __forceinline__ u64 swp(u64 u) { float x, y; upk(u, x, y); return pk(y, x); }
__device__ __forceinline__ u64 ffma2(u64 a, u64 b, u64 c) {
    u64 d; asm("fma.rn.f32x2 %0, %1, %2, %3;" : "=l"(d) : "l"(a), "l"(b), "l"(c)); return d;
}
__device__ __forceinline__ u64 fmul2(u64 a, u64 b) {
    u64 d; asm("mul.rn.f32x2 %0, %1, %2;" : "=l"(d) : "l"(a), "l"(b)); return d;
}

// amp j = (w<<8)|(lh<<6)|(a<<3)|b ; qubit i <-> j bit (9-i)
// Layout A: lane=(lh<<3)|ll, reg r holds amp(a=r, b=ll)  [reg qubits 4,5,6]
// Layout B: lane=(lh<<3)|ll, reg r holds amp(a=ll, b=r)  [reg qubits 7,8,9]
// slot(w,lh,a,b) = (w<<8)|(lh<<6)|((b^lh)<<3)|(a^b)   (conflict-free both layouts)

struct Ctx {
    u64*    s_x0;
    u64*    s_x1;
    float2* s_rot;
    float*  s_lane;
    float2* s_f2;       // exp(i * rp(r,k)) per step, 88 entries/step
    float*  s_w;
};

// One full time step, parity PAR (0: enters layout A; flips mid-step)
template<int PAR>
__device__ __forceinline__ void do_step(int tt, u64 (&psi)[AMPS], const Ctx& C,
                                        int w, int lane, int lh, int ll, int k0)
{
    // ---- diagonal E_tt: psi *= exp(i*base) * exp(i*rp) ----
    {
        float bph = C.s_lane[tt * 32 + lane] + C.s_w[tt * 4 + w];
        float sb, cb; __sincosf(bph, &sb, &cb);      // ONE sincos per step
        u64 A1 = pk(cb, cb), B1 = pk(-sb, sb);
        const float2* fp = C.s_f2 + tt * 88 + k0;
        #pragma unroll
        for (int r = 0; r < AMPS; r++) {
            float2 f = fp[r * 11 + __popc(r)];
            u64 A2 = pk(f.x, f.x), B2 = pk(-f.y, f.y);
            u64 t = ffma2(B2, swp(psi[r]), fmul2(A2, psi[r]));
            psi[r]  = ffma2(B1, swp(t),      fmul2(A1, t));
        }
    }
    // ---- shuffle gates: qubits 2,3 (lane masks 16,8) ----
    #pragma unroll
    for (int q = 2; q < 4; q++) {
        const int m = 1 << (6 - q);
        float2 cs = C.s_rot[tt * NQ + q];
        float so = (lane & m) ? cs.y : -cs.y;
        u64 C2 = pk(cs.x, cs.x), S2 = pk(so, so);
        #pragma unroll
        for (int r = 0; r < AMPS; r++) {
            float x, y; upk(psi[r], x, y);
            float ox = __shfl_xor_sync(0xFFFFFFFFu, x, m);
            float oy = __shfl_xor_sync(0xFFFFFFFFu, y, m);
            psi[r] = ffma2(S2, pk(ox, oy), fmul2(C2, psi[r]));
        }
    }
    // ---- reg triple 1 (entry layout): qubits (PAR?7:4)+qq, masks 4,2,1 ----
    {
        const int qb1 = PAR ? 7 : 4;
        #pragma unroll
        for (int qq = 0; qq < 3; qq++) {
            const int m = 4 >> qq;
            float2 cs = C.s_rot[tt * NQ + qb1 + qq];
            u64 C2 = pk(cs.x, cs.x), S2 = pk(cs.y, cs.y), Sn = pk(-cs.y, -cs.y);
            #pragma unroll
            for (int rr = 0; rr < AMPS / 2; rr++) {
                int r0 = ((rr & ~(m - 1)) << 1) | (rr & (m - 1));
                int r1 = r0 | m;
                u64 p0 = psi[r0], p1 = psi[r1];
                psi[r0] = ffma2(Sn, p1, fmul2(C2, p0));
                psi[r1] = ffma2(S2, p0, fmul2(C2, p1));
            }
        }
    }
    // ---- combined q0 (x) q1 4-way exchange WITH layout flip, 1 barrier ----
    {
        u64* buf = PAR ? C.s_x1 : C.s_x0;
        float2 cs0 = C.s_rot[tt * NQ + 0];   // qubit 0 = w bit 1
        float2 cs1 = C.s_rot[tt * NQ + 1];   // qubit 1 = w bit 0
        const int x1 = (w >> 1) & 1;
        const int x0 = w & 1;
        float g0a = cs0.x, g0b = x1 ? cs0.y : -cs0.y;
        float g1a = cs1.x, g1b = x0 ? cs1.y : -cs1.y;
        float k0c = (x1 == 0 ? g0a : g0b) * (x0 == 0 ? g1a : g1b);
        float k1c = (x1 == 0 ? g0a : g0b) * (x0 == 1 ? g1a : g1b);
        float k2c = (x1 == 1 ? g0a : g0b) * (x0 == 0 ? g1a : g1b);
        float k3c = (x1 == 1 ? g0a : g0b) * (x0 == 1 ? g1a : g1b);
        u64 K0 = pk(k0c, k0c), K1 = pk(k1c, k1c), K2 = pk(k2c, k2c), K3 = pk(k3c, k3c);

        const int wbase = (w << 8) | (lh << 6);
        #pragma unroll
        for (int r = 0; r < AMPS; r++) {
            const int p = PAR ? (r ^ lh) : (ll ^ lh);
            buf[wbase | (p << 3) | (r ^ ll)] = psi[r];
        }
        __syncthreads();
        #pragma unroll
        for (int r = 0; r < AMPS; r++) {
            const int p  = PAR ? (ll ^ lh) : (r ^ lh);
            const int lo = (lh << 6) | (p << 3) | (r ^ ll);
            u64 acc =  fmul2(K0, buf[lo]);
            acc = ffma2(K1, buf[(1 << 8) | lo], acc);
            acc = ffma2(K2, buf[(2 << 8) | lo], acc);
            acc = ffma2(K3, buf[(3 << 8) | lo], acc);
            psi[r] = acc;
        }
    }
    // ---- reg triple 2 (flipped layout): the other qubit triple ----
    {
        const int qb2 = PAR ? 4 : 7;
        #pragma unroll
        for (int qq = 0; qq < 3; qq++) {
            const int m = 4 >> qq;
            float2 cs = C.s_rot[tt * NQ + qb2 + qq];
            u64 C2 = pk(cs.x, cs.x), S2 = pk(cs.y, cs.y), Sn = pk(-cs.y, -cs.y);
            #pragma unroll
            for (int rr = 0; rr < AMPS / 2; rr++) {
                int r0 = ((rr & ~(m - 1)) << 1) | (rr & (m - 1));
                int r1 = r0 | m;
                u64 p0 = psi[r0], p1 = psi[r1];
                psi[r0] = ffma2(Sn, p1, fmul2(C2, p0));
                psi[r1] = ffma2(S2, p0, fmul2(C2, p1));
            }
        }
    }
}

__global__ __launch_bounds__(NTHREADS, 8)
void scramble_kernel(const float* __restrict__ in_re,
                     const float* __restrict__ in_im,
                     const float* __restrict__ phis,
                     const float* __restrict__ gs,
                     float* __restrict__ out)
{
    __shared__ u64    s_x[2][DIM];
    __shared__ float2 s_rot[TSTEPS * NQ];     // (cos(th/2), sin(th/2))
    __shared__ float  s_wgt[11][NQ];          // merged diag weights
    __shared__ float  s_lane[11 * 32];        // layout-aware lane sums
    __shared__ float2 s_f2[11 * 8 * 11];      // exp(i*(reg-sum + popcount phase))
    __shared__ float  s_w[11 * 4];            // w sums + (-0.5*total)
    __shared__ float  s_nrm[4];

    const int tid  = threadIdx.x;
    const int w    = tid >> 5;
    const int lane = tid & 31;
    const int lh   = lane >> 3;
    const int ll   = lane & 7;
    const int b    = blockIdx.x;
    const float* P = phis + b * 300;

    // ---- rotation coefficients ----
    if (tid < 100) {
        int tt = tid / NQ, i = tid - tt * NQ;
        float th = P[30 * tt + NQ + i];
        float s, c; __sincosf(0.5f * th, &s, &c);
        s_rot[tid] = make_float2(c, s);
    }
    // ---- merged diag weights w_i(t) = a_i(t) + b_i(t-1) ----
    if (tid < 110) {
        int tt = tid / NQ, i = tid - tt * NQ;
        float v = 0.f;
        if (tt < 10) v += P[30 * tt + i];
        if (tt > 0)  v += P[30 * (tt - 1) + 2 * NQ + i];
        s_wgt[tt][i] = v;
    }
    __syncthreads();
    // ---- lane-sum tables (entry layout of step tt: A if tt even) ----
    for (int idx = tid; idx < 11 * 32; idx += NTHREADS) {
        int tt = idx >> 5, l = idx & 31, la = tt & 1;
        float s = 0.f;
        if (l & 16) s += s_wgt[tt][2];
        if (l & 8)  s += s_wgt[tt][3];
        if (la == 0) {   // A: lane low bits = b-field -> qubits 7,8,9
            if (l & 4) s += s_wgt[tt][7];
            if (l & 2) s += s_wgt[tt][8];
            if (l & 1) s += s_wgt[tt][9];
        } else {         // B: lane low bits = a-field -> qubits 4,5,6
            if (l & 4) s += s_wgt[tt][4];
            if (l & 2) s += s_wgt[tt][5];
            if (l & 1) s += s_wgt[tt][6];
        }
        s_lane[idx] = s;
    }
    // ---- w-sum tables ----
    for (int idx = tid; idx < 11 * 4; idx += NTHREADS) {
        int tt = idx >> 2, ww = idx & 3;
        float tot = 0.f;
        #pragma unroll
        for (int i = 0; i < NQ; i++) tot += s_wgt[tt][i];
        float s = -0.5f * tot;
        if (ww & 1) s += s_wgt[tt][1];
        if (ww & 2) s += s_wgt[tt][0];
        s_w[idx] = s;
    }
    // ---- complex reg-sum * popcount-phase factor tables ----
    for (int idx = tid; idx < 11 * 8 * 11; idx += NTHREADS) {
        int tt = idx / 88, rem = idx - tt * 88;
        int r = rem / 11, k = rem - r * 11, la = tt & 1;
        float v = 0.f;
        if (la == 0) {   // A: r = a-field -> qubits 4,5,6
            if (r & 4) v += s_wgt[tt][4];
            if (r & 2) v += s_wgt[tt][5];
            if (r & 1) v += s_wgt[tt][6];
        } else {         // B: r = b-field -> qubits 7,8,9
            if (r & 4) v += s_wgt[tt][7];
            if (r & 2) v += s_wgt[tt][8];
            if (r & 1) v += s_wgt[tt][9];
        }
        if (tt > 0) {
            const float inv = 0.15811388300841897f;  // 1/(2*sqrt(10))
            float theta = gs[b * TSTEPS + tt - 1] * inv;
            float zs = 10.f - 2.f * (float)k;
            v += -0.5f * theta * (0.5f * (zs * zs - 10.f));
        }
        float sv, cv; __sincosf(v, &sv, &cv);
        s_f2[idx] = make_float2(cv, sv);
    }

    // ---- load amplitudes (layout A) + norm ----
    u64 psi[AMPS];
    float nrm = 0.f;
    #pragma unroll
    for (int r = 0; r < AMPS; r++) {
        int j = (w << 8) | (lh << 6) | (r << 3) | ll;
        float re = in_re[b * DIM + j];
        float im = in_im[b * DIM + j];
        psi[r] = pk(re, im);
        nrm += re * re + im * im;
    }
    #pragma unroll
    for (int off = 16; off; off >>= 1)
        nrm += __shfl_xor_sync(0xFFFFFFFFu, nrm, off);
    if (lane == 0) s_nrm[w] = nrm;
    __syncthreads();                           // also fences table builds
    const float invn = rsqrtf(s_nrm[0] + s_nrm[1] + s_nrm[2] + s_nrm[3]);
    const int k0 = __popc(lane) + __popc(w);

    Ctx C{ s_x[0], s_x[1], s_rot, s_lane, s_f2, s_w };

    // ---- 10 steps, parity specialized; one barrier per step ----
    #pragma unroll 1
    for (int th = 0; th < TSTEPS / 2; th++) {
        do_step<0>(2 * th,     psi, C, w, lane, lh, ll, k0);
        do_step<1>(2 * th + 1, psi, C, w, lane, lh, ll, k0);
    }

    // ---- final diagonal E_10 (layout A) ----
    {
        float bph = s_lane[10 * 32 + lane] + s_w[10 * 4 + w];
        float sb, cb; __sincosf(bph, &sb, &cb);
        u64 A1 = pk(cb, cb), B1 = pk(-sb, sb);
        const float2* fp = s_f2 + 10 * 88 + k0;
        #pragma unroll
        for (int r = 0; r < AMPS; r++) {
            float2 f = fp[r * 11 + __popc(r)];
            u64 A2 = pk(f.x, f.x), B2 = pk(-f.y, f.y);
            u64 t = ffma2(B2, swp(psi[r]), fmul2(A2, psi[r]));
            psi[r]  = ffma2(B1, swp(t),      fmul2(A1, t));
        }
    }
    // ---- store (layout A) with deferred normalization ----
    #pragma unroll
    for (int r = 0; r < AMPS; r++) {
        int j = (w << 8) | (lh << 6) | (r << 3) | ll;
        float x, y; upk(psi[r], x, y);
        out[b * DIM + j]               = x * invn;
        out[NDATA * DIM + b * DIM + j] = y * invn;
    }
}

extern "C" void kernel_launch(void* const* d_in, const int* in_sizes, int n_in,
                              void* d_out, int out_size)
{
    const float* in_re = (const float*)d_in[0];
    const float* in_im = (const float*)d_in[1];
    const float* phis  = (const float*)d_in[2];
    const float* gs    = (const float*)d_in[3];
    float* out = (float*)d_out;
    scramble_kernel<<<NDATA, NTHREADS>>>(in_re, in_im, phis, gs, out);
}

// round 17
// speedup vs baseline: 1.7690x; 1.0749x over previous
#include <cuda_runtime.h>

#define NQ      10
#define DIM     1024
#define TSTEPS  10
#define NDATA   1024
#define NTHREADS 128               // 4 warps = 1 sample
#define AMPS    8

typedef unsigned long long u64;

__device__ __forceinline__ u64 pk(float x, float y) {
    u64 u; asm("mov.b64 %0, {%1,%2};" : "=l"(u) : "f"(x), "f"(y)); return u;
}
__device__ __forceinline__ void upk(u64 u, float &x, float &y) {
    asm("mov.b64 {%0,%1}, %2;" : "=f"(x), "=f"(y) : "l"(u));
}
__device__ __forceinline__ u64 swp(u64 u) { float x, y; upk(u, x, y); return pk(y, x); }
__device__ __forceinline__ u64 ffma2(u64 a, u64 b, u64 c) {
    u64 d; asm("fma.rn.f32x2 %0, %1, %2, %3;" : "=l"(d) : "l"(a), "l"(b), "l"(c)); return d;
}
__device__ __forceinline__ u64 fmul2(u64 a, u64 b) {
    u64 d; asm("mul.rn.f32x2 %0, %1, %2;" : "=l"(d) : "l"(a), "l"(b)); return d;
}

// amp j = (w<<8)|(lh<<6)|(a<<3)|b ; qubit i <-> j bit (9-i)
// Layout A: lane=(lh<<3)|ll, reg r holds amp(a=r, b=ll)  [reg qubits 4,5,6]
// Layout B: lane=(lh<<3)|ll, reg r holds amp(a=ll, b=r)  [reg qubits 7,8,9]
// slot(w,lh,a,b) = (w<<8)|(lh<<6)|((b^lh)<<3)|(a^b)   (conflict-free both layouts)

struct Ctx {
    u64*    s_x0;
    u64*    s_x1;
    float2* s_rot;
    float*  s_lane;
    float*  s_w;
    float*  s_wgt;      // [11*NQ] merged diag weights
    float4* s_quad;     // [11] (p2,p1,p0,_) : phi(k) = (p2*k+p1)*k+p0
};

// One full time step, parity PAR (0: enters layout A; flips mid-step)
template<int PAR>
__device__ __forceinline__ void do_step(int tt, u64 (&psi)[AMPS], const Ctx& C,
                                        int w, int lane, int lh, int ll, int k0)
{
    // ---- diagonal E_tt: phase = base(lane,w) + regsum(r) + phi(k0+popc(r)) ----
    {
        const float wA = C.s_wgt[tt * NQ + (PAR ? 7 : 4)];
        const float wB = C.s_wgt[tt * NQ + (PAR ? 8 : 5)];
        const float wC = C.s_wgt[tt * NQ + (PAR ? 9 : 6)];
        const float4 qd = C.s_quad[tt];
        const float base = C.s_lane[tt * 32 + lane] + C.s_w[tt * 4 + w];
        // phi for k = k0 + c, c = 0..3 (popc(r) for r<8)
        float fk  = (float)k0;
        float ph0 = (qd.x * fk + qd.y) * fk + qd.z;
        float fk1 = fk + 1.f;
        float ph1 = (qd.x * fk1 + qd.y) * fk1 + qd.z;
        float fk2 = fk + 2.f;
        float ph2 = (qd.x * fk2 + qd.y) * fk2 + qd.z;
        float fk3 = fk + 3.f;
        float ph3 = (qd.x * fk3 + qd.y) * fk3 + qd.z;
        // regsums for r = 0..7 (bit2->wA, bit1->wB, bit0->wC)
        float rsBC = wB + wC, rsAC = wA + wC, rsAB = wA + wB, rsABC = wA + rsBC;
        float ph[8];
        ph[0] = base + ph0;
        ph[1] = base + wC   + ph1;
        ph[2] = base + wB   + ph1;
        ph[3] = base + rsBC + ph2;
        ph[4] = base + wA   + ph1;
        ph[5] = base + rsAC + ph2;
        ph[6] = base + rsAB + ph2;
        ph[7] = base + rsABC+ ph3;
        #pragma unroll
        for (int r = 0; r < AMPS; r++) {
            float sn, cn; __sincosf(ph[r], &sn, &cn);
            psi[r] = ffma2(pk(-sn, sn), swp(psi[r]), fmul2(pk(cn, cn), psi[r]));
        }
    }
    // ---- shuffle gates: qubits 2,3 (lane masks 16,8), u64-native shuffles ----
    #pragma unroll
    for (int q = 2; q < 4; q++) {
        const int m = 1 << (6 - q);
        float2 cs = C.s_rot[tt * NQ + q];
        float so = (lane & m) ? cs.y : -cs.y;
        u64 C2 = pk(cs.x, cs.x), S2 = pk(so, so);
        #pragma unroll
        for (int r = 0; r < AMPS; r++) {
            u64 oth = __shfl_xor_sync(0xFFFFFFFFu, psi[r], m);
            psi[r] = ffma2(S2, oth, fmul2(C2, psi[r]));
        }
    }
    // ---- reg triple 1 (entry layout): qubits (PAR?7:4)+qq, masks 4,2,1 ----
    {
        const int qb1 = PAR ? 7 : 4;
        #pragma unroll
        for (int qq = 0; qq < 3; qq++) {
            const int m = 4 >> qq;
            float2 cs = C.s_rot[tt * NQ + qb1 + qq];
            u64 C2 = pk(cs.x, cs.x), S2 = pk(cs.y, cs.y), Sn = pk(-cs.y, -cs.y);
            #pragma unroll
            for (int rr = 0; rr < AMPS / 2; rr++) {
                int r0 = ((rr & ~(m - 1)) << 1) | (rr & (m - 1));
                int r1 = r0 | m;
                u64 p0 = psi[r0], p1 = psi[r1];
                psi[r0] = ffma2(Sn, p1, fmul2(C2, p0));
                psi[r1] = ffma2(S2, p0, fmul2(C2, p1));
            }
        }
    }
    // ---- combined q0 (x) q1 4-way exchange WITH layout flip, 1 barrier ----
    {
        u64* buf = PAR ? C.s_x1 : C.s_x0;
        float2 cs0 = C.s_rot[tt * NQ + 0];   // qubit 0 = w bit 1
        float2 cs1 = C.s_rot[tt * NQ + 1];   // qubit 1 = w bit 0
        const int x1 = (w >> 1) & 1;
        const int x0 = w & 1;
        float g0a = cs0.x, g0b = x1 ? cs0.y : -cs0.y;
        float g1a = cs1.x, g1b = x0 ? cs1.y : -cs1.y;
        float k0c = (x1 == 0 ? g0a : g0b) * (x0 == 0 ? g1a : g1b);
        float k1c = (x1 == 0 ? g0a : g0b) * (x0 == 1 ? g1a : g1b);
        float k2c = (x1 == 1 ? g0a : g0b) * (x0 == 0 ? g1a : g1b);
        float k3c = (x1 == 1 ? g0a : g0b) * (x0 == 1 ? g1a : g1b);
        u64 K0 = pk(k0c, k0c), K1 = pk(k1c, k1c), K2 = pk(k2c, k2c), K3 = pk(k3c, k3c);

        const int wbase = (w << 8) | (lh << 6);
        #pragma unroll
        for (int r = 0; r < AMPS; r++) {
            const int p = PAR ? (r ^ lh) : (ll ^ lh);
            buf[wbase | (p << 3) | (r ^ ll)] = psi[r];
        }
        __syncthreads();
        #pragma unroll
        for (int r = 0; r < AMPS; r++) {
            const int p  = PAR ? (ll ^ lh) : (r ^ lh);
            const int lo = (lh << 6) | (p << 3) | (r ^ ll);
            u64 acc =  fmul2(K0, buf[lo]);
            acc = ffma2(K1, buf[(1 << 8) | lo], acc);
            acc = ffma2(K2, buf[(2 << 8) | lo], acc);
            acc = ffma2(K3, buf[(3 << 8) | lo], acc);
            psi[r] = acc;
        }
    }
    // ---- reg triple 2 (flipped layout): the other qubit triple ----
    {
        const int qb2 = PAR ? 4 : 7;
        #pragma unroll
        for (int qq = 0; qq < 3; qq++) {
            const int m = 4 >> qq;
            float2 cs = C.s_rot[tt * NQ + qb2 + qq];
            u64 C2 = pk(cs.x, cs.x), S2 = pk(cs.y, cs.y), Sn = pk(-cs.y, -cs.y);
            #pragma unroll
            for (int rr = 0; rr < AMPS / 2; rr++) {
                int r0 = ((rr & ~(m - 1)) << 1) | (rr & (m - 1));
                int r1 = r0 | m;
                u64 p0 = psi[r0], p1 = psi[r1];
                psi[r0] = ffma2(Sn, p1, fmul2(C2, p0));
                psi[r1] = ffma2(S2, p0, fmul2(C2, p1));
            }
        }
    }
}

__global__ __launch_bounds__(NTHREADS, 8)
void scramble_kernel(const float* __restrict__ in_re,
                     const float* __restrict__ in_im,
                     const float* __restrict__ phis,
                     const float* __restrict__ gs,
                     float* __restrict__ out)
{
    __shared__ u64    s_x[2][DIM];
    __shared__ float2 s_rot[TSTEPS * NQ];     // (cos(th/2), sin(th/2))
    __shared__ float  s_wgt[11 * NQ];         // merged diag weights
    __shared__ float  s_lane[11 * 32];        // layout-aware lane sums
    __shared__ float  s_w[11 * 4];            // w sums + (-0.5*total)
    __shared__ float4 s_quad[11];             // phi(k) quadratic coefficients
    __shared__ float  s_nrm[4];

    const int tid  = threadIdx.x;
    const int w    = tid >> 5;
    const int lane = tid & 31;
    const int lh   = lane >> 3;
    const int ll   = lane & 7;
    const int b    = blockIdx.x;
    const float* P = phis + b * 300;

    // ---- rotation coefficients ----
    if (tid < 100) {
        int tt = tid / NQ, i = tid - tt * NQ;
        float th = P[30 * tt + NQ + i];
        float s, c; __sincosf(0.5f * th, &s, &c);
        s_rot[tid] = make_float2(c, s);
    }
    // ---- merged diag weights w_i(t) = a_i(t) + b_i(t-1) ----
    if (tid < 110) {
        int tt = tid / NQ, i = tid - tt * NQ;
        float v = 0.f;
        if (tt < 10) v += P[30 * tt + i];
        if (tt > 0)  v += P[30 * (tt - 1) + 2 * NQ + i];
        s_wgt[tt * NQ + i] = v;
    }
    // ---- phi quadratic per step: phi(k) = ta*(-k^2 + 10k - 22.5) ----
    if (tid < 11) {
        float ta = 0.f;
        if (tid > 0) ta = gs[b * TSTEPS + tid - 1] * 0.15811388300841897f;
        s_quad[tid] = make_float4(-ta, 10.f * ta, -22.5f * ta, 0.f);
    }
    __syncthreads();
    // ---- lane-sum tables (entry layout of step tt: A if tt even) ----
    for (int idx = tid; idx < 11 * 32; idx += NTHREADS) {
        int tt = idx >> 5, l = idx & 31, la = tt & 1;
        float s = 0.f;
        if (l & 16) s += s_wgt[tt * NQ + 2];
        if (l & 8)  s += s_wgt[tt * NQ + 3];
        if (la == 0) {   // A: lane low bits = b-field -> qubits 7,8,9
            if (l & 4) s += s_wgt[tt * NQ + 7];
            if (l & 2) s += s_wgt[tt * NQ + 8];
            if (l & 1) s += s_wgt[tt * NQ + 9];
        } else {         // B: lane low bits = a-field -> qubits 4,5,6
            if (l & 4) s += s_wgt[tt * NQ + 4];
            if (l & 2) s += s_wgt[tt * NQ + 5];
            if (l & 1) s += s_wgt[tt * NQ + 6];
        }
        s_lane[idx] = s;
    }
    // ---- w-sum tables ----
    for (int idx = tid; idx < 11 * 4; idx += NTHREADS) {
        int tt = idx >> 2, ww = idx & 3;
        float tot = 0.f;
        #pragma unroll
        for (int i = 0; i < NQ; i++) tot += s_wgt[tt * NQ + i];
        float s = -0.5f * tot;
        if (ww & 1) s += s_wgt[tt * NQ + 1];
        if (ww & 2) s += s_wgt[tt * NQ + 0];
        s_w[idx] = s;
    }

    // ---- load amplitudes (layout A) + norm ----
    u64 psi[AMPS];
    float nrm = 0.f;
    #pragma unroll
    for (int r = 0; r < AMPS; r++) {
        int j = (w << 8) | (lh << 6) | (r << 3) | ll;
        float re = in_re[b * DIM + j];
        float im = in_im[b * DIM + j];
        psi[r] = pk(re, im);
        nrm += re * re + im * im;
    }
    #pragma unroll
    for (int off = 16; off; off >>= 1)
        nrm += __shfl_xor_sync(0xFFFFFFFFu, nrm, off);
    if (lane == 0) s_nrm[w] = nrm;
    __syncthreads();                           // also fences table builds
    const float invn = rsqrtf(s_nrm[0] + s_nrm[1] + s_nrm[2] + s_nrm[3]);
    const int k0 = __popc(lane) + __popc(w);

    Ctx C{ s_x[0], s_x[1], s_rot, s_lane, s_w, s_wgt, s_quad };

    // ---- 10 steps, parity specialized; one barrier per step ----
    #pragma unroll 1
    for (int th = 0; th < TSTEPS / 2; th++) {
        do_step<0>(2 * th,     psi, C, w, lane, lh, ll, k0);
        do_step<1>(2 * th + 1, psi, C, w, lane, lh, ll, k0);
    }

    // ---- final diagonal E_10 (layout A: r-field = qubits 4,5,6) ----
    {
        const float wA = s_wgt[10 * NQ + 4];
        const float wB = s_wgt[10 * NQ + 5];
        const float wC = s_wgt[10 * NQ + 6];
        const float4 qd = s_quad[10];
        const float base = s_lane[10 * 32 + lane] + s_w[10 * 4 + w];
        float fk  = (float)k0;
        float ph0 = (qd.x * fk + qd.y) * fk + qd.z;
        float fk1 = fk + 1.f;
        float ph1 = (qd.x * fk1 + qd.y) * fk1 + qd.z;
        float fk2 = fk + 2.f;
        float ph2 = (qd.x * fk2 + qd.y) * fk2 + qd.z;
        float fk3 = fk + 3.f;
        float ph3 = (qd.x * fk3 + qd.y) * fk3 + qd.z;
        float rsBC = wB + wC, rsAC = wA + wC, rsAB = wA + wB, rsABC = wA + rsBC;
        float ph[8];
        ph[0] = base + ph0;
        ph[1] = base + wC   + ph1;
        ph[2] = base + wB   + ph1;
        ph[3] = base + rsBC + ph2;
        ph[4] = base + wA   + ph1;
        ph[5] = base + rsAC + ph2;
        ph[6] = base + rsAB + ph2;
        ph[7] = base + rsABC+ ph3;
        #pragma unroll
        for (int r = 0; r < AMPS; r++) {
            float sn, cn; __sincosf(ph[r], &sn, &cn);
            psi[r] = ffma2(pk(-sn, sn), swp(psi[r]), fmul2(pk(cn, cn), psi[r]));
        }
    }
    // ---- store (layout A) with deferred normalization ----
    #pragma unroll
    for (int r = 0; r < AMPS; r++) {
        int j = (w << 8) | (lh << 6) | (r << 3) | ll;
        float x, y; upk(psi[r], x, y);
        out[b * DIM + j]               = x * invn;
        out[NDATA * DIM + b * DIM + j] = y * invn;
    }
}

extern "C" void kernel_launch(void* const* d_in, const int* in_sizes, int n_in,
                              void* d_out, int out_size)
{
    const float* in_re = (const float*)d_in[0];
    const float* in_im = (const float*)d_in[1];
    const float* phis  = (const float*)d_in[2];
    const float* gs    = (const float*)d_in[3];
    float* out = (float*)d_out;
    scramble_kernel<<<NDATA, NTHREADS>>>(in_re, in_im, phis, gs, out);
}